// round 8
// baseline (speedup 1.0000x reference)
#include <cuda_runtime.h>
#include <cstdint>

// Problem constants
#define B_   4
#define TE   512
#define TD   256
#define DE   512
#define DD   512
#define U_   128
#define NROW_E (B_*TE)   // 2048 encoder rows
#define NROW_D (B_*TD)   // 1024 decoder rows
#define TT   4           // decoder-t tile per attn block
#define CTX_OFF (NROW_D*DE)   // context elements before attn weights in d_out

typedef unsigned long long ull;

// Scratch (static device globals: no allocation allowed)
__device__ float g_encT[U_ * NROW_E];   // enc projection, TRANSPOSED: [u][row]
__device__ float g_dec [NROW_D * U_];   // dec projection: [row][u]

__device__ __forceinline__ float tanh_fast(float x) {
    float y;
    asm("tanh.approx.f32 %0, %1;" : "=f"(y) : "f"(x));
    return y;
}

#define FMA_F32X2(d, a, b) \
    asm("fma.rn.f32x2 %0, %1, %2, %0;" : "+l"(d) : "l"(a), "l"(b))

__device__ __forceinline__ ull pack2(float lo, float hi) {
    ull r;
    asm("mov.b64 %0, {%1, %2};" : "=l"(r) : "f"(lo), "f"(hi));
    return r;
}

// ---------------------------------------------------------------------------
// Kernel 1: both input projections, f32x2 row-pair packed.
//   enc_p[row,u] = enc[row,:] @ W1[:,u] + b1[u]   (stored transposed [u][row])
//   dec_p[row,u] = dec[row,:] @ W2[:,u] + b2[u]   (stored [row][u])
// Grid: 2048/32 + 1024/32 = 96 blocks, 256 threads, 32 rows/block (1 wave).
// X held in smem transposed+paired: sXP[kk][34] (pairs of rows, 8B-aligned).
// W streamed through a 64-k smem chunk so the hot loop is all-LDS.
// Per k: 1 LDS(w) + 1 pack + 8 LDS.64 + 8 FMA2 = 18 instr for 32 row-outputs.
// ---------------------------------------------------------------------------
#define PROJ_ROWS 32
#define KCHUNK 64
__global__ __launch_bounds__(256) void proj_kernel(
    const float* __restrict__ enc, const float* __restrict__ dec,
    const float* __restrict__ W1, const float* __restrict__ b1,
    const float* __restrict__ W2, const float* __restrict__ b2)
{
    __shared__ float sXP[KCHUNK * 34];     // [kk][32 rows + 2 pad] transposed X chunk
    __shared__ float Wc [KCHUNK * U_];     // [kk][u] W chunk

    const int ENC_BLOCKS = NROW_E / PROJ_ROWS;   // 64
    bool isDec = (blockIdx.x >= ENC_BLOCKS);
    int rowBase = (isDec ? (blockIdx.x - ENC_BLOCKS) : blockIdx.x) * PROJ_ROWS;

    const float* X    = isDec ? dec : enc;
    const float* W    = isDec ? W2  : W1;
    const float* bias = isDec ? b2  : b1;

    int u  = threadIdx.x & 127;
    int rg = threadIdx.x >> 7;   // pairs [rg*8, rg*8+8) -> rows [rg*16, rg*16+16)

    float bv = bias[u];
    ull acc[8];
#pragma unroll
    for (int p = 0; p < 8; p++) acc[p] = pack2(bv, bv);

    for (int kc = 0; kc < 512; kc += KCHUNK) {
        __syncthreads();   // previous chunk fully consumed
        // fill W chunk: 64 k x 128 u = 2048 float4 / 256 thr = 8 each
        for (int i4 = threadIdx.x; i4 < KCHUNK * 32; i4 += 256) {
            int kk = i4 >> 5, u4 = i4 & 31;
            ((float4*)Wc)[kk * 32 + u4] =
                ((const float4*)(W + (size_t)(kc + kk) * U_))[u4];
        }
        // fill X chunk transposed: 32 rows x 64 k = 512 float4 / 256 thr = 2 each
        for (int i4 = threadIdx.x; i4 < PROJ_ROWS * (KCHUNK / 4); i4 += 256) {
            int row = i4 >> 4, kl4 = i4 & 15;
            float4 v = ((const float4*)(X + (size_t)(rowBase + row) * 512 + kc))[kl4];
            sXP[(kl4 * 4 + 0) * 34 + row] = v.x;
            sXP[(kl4 * 4 + 1) * 34 + row] = v.y;
            sXP[(kl4 * 4 + 2) * 34 + row] = v.z;
            sXP[(kl4 * 4 + 3) * 34 + row] = v.w;
        }
        __syncthreads();

#pragma unroll 4
        for (int kk = 0; kk < KCHUNK; kk++) {
            float wv = Wc[kk * U_ + u];              // conflict-free (stride 1 over u)
            ull  wvv = pack2(wv, wv);
            const float* xb = &sXP[kk * 34 + rg * 16];
#pragma unroll
            for (int p = 0; p < 8; p++)
                FMA_F32X2(acc[p], *(const ull*)(xb + 2 * p), wvv);  // broadcast LDS.64
        }
    }

    if (!isDec) {
        // rows consecutive in g_encT[u][row] -> STG.64 pairs
#pragma unroll
        for (int p = 0; p < 8; p++)
            *(ull*)&g_encT[(size_t)u * NROW_E + rowBase + rg * 16 + 2 * p] = acc[p];
    } else {
#pragma unroll
        for (int p = 0; p < 8; p++) {
            float lo, hi;
            asm("mov.b64 {%0, %1}, %2;" : "=f"(lo), "=f"(hi) : "l"(acc[p]));
            int row = rowBase + rg * 16 + 2 * p;
            g_dec[(size_t)row * U_ + u]       = lo;
            g_dec[(size_t)(row + 1) * U_ + u] = hi;
        }
    }
}

// ---------------------------------------------------------------------------
// Kernel 2: fused score + softmax + context for a (b, 4-t tile).
// Grid: B * (TD/TT) = 256 blocks, 1024 threads, 2 blocks/SM.
//   Score:   u-split. thread = (e = tid&511, half = tid>>9); half owns 64 u's,
//            computes ALL 4 t's via one LDS.128 of sdpT[u][0..3] per u.
//            Partials exchanged through s_w, then t-split (2 t's) for softmax.
//   Context: thread = (d, half); half owns 256 e's; partials via s_w.
// ---------------------------------------------------------------------------
__global__ __launch_bounds__(1024, 2) void attn_kernel(
    const float* __restrict__ enc,
    const float* __restrict__ Vw,
    float* __restrict__ out)
{
    __shared__ __align__(16) float sdpT[U_][TT];  // dec_p tile TRANSPOSED [u][t]
    __shared__ float sV[U_];
    __shared__ float sred[TT * 16];
    __shared__ float smax[TT];
    __shared__ float ssum[TT];
    __shared__ __align__(16) float s_w[TE][TT];   // partials -> weights -> ctx partials

    int b  = blockIdx.x >> 6;                // / (TD/TT = 64)
    int t0 = (blockIdx.x & 63) * TT;
    int tid  = threadIdx.x;
    int half = tid >> 9;                     // 0 or 1
    int eth  = tid & 511;                    // e (score) / d (context)

    // load dec_p tile transposed (t,u)->(u,t), + V
    if (tid < TT * U_) {
        int t = tid >> 7, u = tid & 127;
        sdpT[u][t] = g_dec[(size_t)(b * TD + t0) * U_ + tid];  // coalesced read
    }
    if (tid < U_) sV[tid] = Vw[tid];
    __syncthreads();

    // ---- score phase: thread owns e = eth, u in [half*64, half*64+64), all 4 t ----
    float a0 = 0.f, a1 = 0.f, a2 = 0.f, a3 = 0.f;
    const int ub = half * 64;
    const float* ep = g_encT + (size_t)ub * NROW_E + (size_t)b * TE + eth;
#pragma unroll 2
    for (int ui = 0; ui < 64; ui++) {
        float  ev = ep[(size_t)ui * NROW_E];              // coalesced, L2-resident
        float4 dp = *(const float4*)&sdpT[ub + ui][0];    // broadcast LDS.128
        float  vv = sV[ub + ui];
        a0 += vv * tanh_fast(ev + dp.x);
        a1 += vv * tanh_fast(ev + dp.y);
        a2 += vv * tanh_fast(ev + dp.z);
        a3 += vv * tanh_fast(ev + dp.w);
    }
    // (V_b dropped: softmax is shift-invariant; cancels in both outputs)

    // exchange partials: write the 2 t's this half does NOT own, read own pair
    const int tb = half * 2;          // this half's softmax t's
    const int ob = 2 - tb;            // the other pair
    *(float2*)&s_w[eth][ob] = half ? make_float2(a0, a1) : make_float2(a2, a3);
    __syncthreads();
    float2 oth = *(const float2*)&s_w[eth][tb];
    float acc0 = (half ? a2 : a0) + oth.x;
    float acc1 = (half ? a3 : a1) + oth.y;

    // ---- softmax over e (512 threads per half), per t ----
    int lane = tid & 31, wid = tid >> 5;     // 32 warps
    int wloc = wid & 15;                     // warp index within half

    // max
    {
        float v0 = acc0, v1 = acc1;
#pragma unroll
        for (int o = 16; o; o >>= 1) {
            v0 = fmaxf(v0, __shfl_xor_sync(0xffffffffu, v0, o));
            v1 = fmaxf(v1, __shfl_xor_sync(0xffffffffu, v1, o));
        }
        if (lane == 0) {
            sred[(tb + 0) * 16 + wloc] = v0;
            sred[(tb + 1) * 16 + wloc] = v1;
        }
    }
    __syncthreads();
    if (wid < TT) {
        float v = (lane < 16) ? sred[wid * 16 + lane] : -3.0e38f;
#pragma unroll
        for (int o = 8; o; o >>= 1)
            v = fmaxf(v, __shfl_xor_sync(0xffffffffu, v, o));
        if (lane == 0) smax[wid] = v;
    }
    __syncthreads();

    // exp + sum
    float p0 = __expf(acc0 - smax[tb + 0]);
    float p1 = __expf(acc1 - smax[tb + 1]);
    {
        float v0 = p0, v1 = p1;
#pragma unroll
        for (int o = 16; o; o >>= 1) {
            v0 += __shfl_xor_sync(0xffffffffu, v0, o);
            v1 += __shfl_xor_sync(0xffffffffu, v1, o);
        }
        if (lane == 0) {
            sred[(tb + 0) * 16 + wloc] = v0;
            sred[(tb + 1) * 16 + wloc] = v1;
        }
    }
    __syncthreads();
    if (wid < TT) {
        float v = (lane < 16) ? sred[wid * 16 + lane] : 0.f;
#pragma unroll
        for (int o = 8; o; o >>= 1)
            v += __shfl_xor_sync(0xffffffffu, v, o);
        if (lane == 0) ssum[wid] = v;
    }
    __syncthreads();

    // weights -> smem [e][t] (for context) and gmem output
    {
        float w0 = p0 / ssum[tb + 0];
        float w1 = p1 / ssum[tb + 1];
        *(float2*)&s_w[eth][tb] = make_float2(w0, w1);
        out[CTX_OFF + (size_t)(b * TD + t0 + tb + 0) * TE + eth] = w0;
        out[CTX_OFF + (size_t)(b * TD + t0 + tb + 1) * TE + eth] = w1;
    }
    __syncthreads();

    // ---- context phase: thread owns d = eth, e-range [half*256, +256) ----
    // context[t,d] = sum_e w[t,e] * enc[b,e,d]; packed f32x2 FMA (2 t per op)
    const float* eb = enc + ((size_t)b * TE + half * 256) * DE + eth;

    ull cc0 = 0ULL, cc1 = 0ULL;
#pragma unroll 4
    for (int ei = 0; ei < 256; ei++) {
        float ev = __ldg(eb + (size_t)ei * DE);     // coalesced, L2-resident
        ull evv = pack2(ev, ev);
        ulonglong2 q = *(const ulonglong2*)&s_w[half * 256 + ei][0]; // (w0,w1),(w2,w3)
        FMA_F32X2(cc0, q.x, evv);
        FMA_F32X2(cc1, q.y, evv);
    }

    float c[TT];
    asm("mov.b64 {%0, %1}, %2;" : "=f"(c[0]), "=f"(c[1]) : "l"(cc0));
    asm("mov.b64 {%0, %1}, %2;" : "=f"(c[2]), "=f"(c[3]) : "l"(cc1));

    // combine the two e-half partials through s_w (weights no longer needed)
    __syncthreads();
    if (half == 1)
        *(float4*)&s_w[eth][0] = make_float4(c[0], c[1], c[2], c[3]);
    __syncthreads();
    if (half == 0) {
        float4 o0 = *(float4*)&s_w[eth][0];
        c[0] += o0.x; c[1] += o0.y; c[2] += o0.z; c[3] += o0.w;
#pragma unroll
        for (int t = 0; t < TT; t++)
            out[(size_t)(b * TD + t0 + t) * DE + eth] = c[t];
    }
}

// ---------------------------------------------------------------------------
extern "C" void kernel_launch(void* const* d_in, const int* in_sizes, int n_in,
                              void* d_out, int out_size)
{
    (void)in_sizes; (void)n_in; (void)out_size;
    const float* enc = (const float*)d_in[0];
    const float* dec = (const float*)d_in[1];
    const float* W1  = (const float*)d_in[2];
    const float* b1  = (const float*)d_in[3];
    const float* W2  = (const float*)d_in[4];
    const float* b2  = (const float*)d_in[5];
    const float* Vw  = (const float*)d_in[6];
    // d_in[7] = V_b: unused (cancels in softmax)
    float* out = (float*)d_out;

    proj_kernel<<<NROW_E / PROJ_ROWS + NROW_D / PROJ_ROWS, 256>>>(
        enc, dec, W1, b1, W2, b2);
    attn_kernel<<<B_ * (TD / TT), 1024>>>(enc, Vw, out);
}